// round 4
// baseline (speedup 1.0000x reference)
#include <cuda_runtime.h>
#include <cuda_bf16.h>
#include <cstdint>

#define S_TOK 8192
#define MDIM  1024
#define EDIM  8
#define HDIM  4096
#define CAP   1024

// ======================= helpers ===========================================
__device__ __forceinline__ uint32_t smem_u32(const void* p) {
    uint32_t a;
    asm("{ .reg .u64 t; cvta.to.shared.u64 t, %1; cvt.u32.u64 %0, t; }" : "=r"(a) : "l"(p));
    return a;
}
__device__ __forceinline__ void cp_async16(uint32_t dst, const void* src) {
    asm volatile("cp.async.cg.shared.global [%0], [%1], 16;" :: "r"(dst), "l"(src));
}
#define CP_COMMIT() asm volatile("cp.async.commit_group;" ::: "memory")
#define CP_WAIT(n)  asm volatile("cp.async.wait_group %0;" :: "n"(n) : "memory")

__device__ __forceinline__ void ldmatrix_x4(uint32_t* r, uint32_t addr) {
    asm volatile("ldmatrix.sync.aligned.m8n8.x4.shared.b16 {%0,%1,%2,%3}, [%4];"
                 : "=r"(r[0]), "=r"(r[1]), "=r"(r[2]), "=r"(r[3]) : "r"(addr));
}
__device__ __forceinline__ void mma_bf16(float* c, const uint32_t* a, uint32_t b0, uint32_t b1) {
    asm volatile("mma.sync.aligned.m16n8k16.row.col.f32.bf16.bf16.f32 "
                 "{%0,%1,%2,%3}, {%4,%5,%6,%7}, {%8,%9}, {%0,%1,%2,%3};"
                 : "+f"(c[0]), "+f"(c[1]), "+f"(c[2]), "+f"(c[3])
                 : "r"(a[0]), "r"(a[1]), "r"(a[2]), "r"(a[3]), "r"(b0), "r"(b1));
}

// split a pair of floats into packed bf16 (hi word, lo word)
__device__ __forceinline__ void split2(float a, float b, uint32_t& hi, uint32_t& lo) {
    __nv_bfloat16 ah = __float2bfloat16_rn(a), bh = __float2bfloat16_rn(b);
    float ar = a - __bfloat162float(ah);
    float br = b - __bfloat162float(bh);
    __nv_bfloat16 al = __float2bfloat16_rn(ar), bl = __float2bfloat16_rn(br);
    hi = (uint32_t)__bfloat16_as_ushort(ah) | ((uint32_t)__bfloat16_as_ushort(bh) << 16);
    lo = (uint32_t)__bfloat16_as_ushort(al) | ((uint32_t)__bfloat16_as_ushort(bl) << 16);
}

// ======================= scratch ===========================================
__device__ float g_gate[S_TOK];
__device__ int   g_exp[S_TOK];
__device__ int   g_loc[S_TOK];
__device__ float g_sumgate[EDIM];
__device__ int   g_count[EDIM];
__device__ float g_laux;
// split-bf16 buffers: one u32 row element = 2 bf16; row = [hi K/2 u32][lo K/2 u32]
__device__ uint32_t g_disp[(size_t)EDIM * CAP * MDIM];     // rows=8192, rowu32=1024 (32MB)
__device__ uint32_t g_h[(size_t)S_TOK * HDIM];             // rows=8192, rowu32=4096 (128MB)
__device__ float    g_eout[(size_t)S_TOK * MDIM];          // fp32 (32MB)
__device__ uint32_t g_w1t[(size_t)EDIM * HDIM * MDIM];     // [e][n=4096][rowu32=1024] (128MB)
__device__ uint32_t g_w2t[(size_t)EDIM * MDIM * HDIM];     // [e][n=1024][rowu32=4096] (128MB)

// ======================= weight transpose + bf16 split =====================
// W[e][K][N] fp32 -> Wt[e][N][hi K bf16, lo K bf16]
template <int K, int N>
__global__ __launch_bounds__(256) void wsplit_kernel(const float* __restrict__ W,
                                                     uint32_t* __restrict__ Wt) {
    __shared__ float tile[32][33];
    int e = blockIdx.z;
    const float* We = W + (size_t)e * K * N;
    uint32_t* Wte = Wt + (size_t)e * N * K;   // rowu32 = K
    int n0 = blockIdx.x * 32, k0 = blockIdx.y * 32;
    int tx = threadIdx.x, ty = threadIdx.y;
#pragma unroll
    for (int j = 0; j < 32; j += 8)
        tile[ty + j][tx] = We[(size_t)(k0 + ty + j) * N + n0 + tx];
    __syncthreads();
    int wid = ty * 32 + tx;
    int kp = wid & 15;          // k-pair 0..15
#pragma unroll
    for (int h = 0; h < 2; h++) {
        int nl = (wid >> 4) + h * 16;
        float v0 = tile[2 * kp][nl];
        float v1 = tile[2 * kp + 1][nl];
        uint32_t hi, lo;
        split2(v0, v1, hi, lo);
        size_t base = (size_t)(n0 + nl) * K + (k0 >> 1) + kp;
        Wte[base] = hi;
        Wte[base + K / 2] = lo;
    }
}

// ======================= init / gating / scan ==============================
__global__ void init_kernel() {
    int t = threadIdx.x;
    if (t < EDIM) { g_sumgate[t] = 0.f; g_count[t] = 0; }
}

__global__ __launch_bounds__(256) void gate_kernel(const float* __restrict__ x,
                                                   const float* __restrict__ wg) {
    __shared__ float swg[MDIM * EDIM];
    __shared__ float ssum[EDIM];
    __shared__ int   scnt[EDIM];
    int tid = threadIdx.x;
    for (int i = tid; i < MDIM * EDIM; i += 256) swg[i] = wg[i];
    if (tid < EDIM) { ssum[tid] = 0.f; scnt[tid] = 0; }
    __syncthreads();

    int warp = tid >> 5, lane = tid & 31;
    int t = blockIdx.x * 8 + warp;
    const float* xr = x + (size_t)t * MDIM;

    float acc[EDIM];
#pragma unroll
    for (int e = 0; e < EDIM; e++) acc[e] = 0.f;
    for (int m = lane; m < MDIM; m += 32) {
        float xv = xr[m];
#pragma unroll
        for (int e = 0; e < EDIM; e++) acc[e] = fmaf(xv, swg[m * EDIM + e], acc[e]);
    }
#pragma unroll
    for (int e = 0; e < EDIM; e++)
#pragma unroll
        for (int o = 16; o > 0; o >>= 1)
            acc[e] += __shfl_xor_sync(0xffffffffu, acc[e], o);

    if (lane == 0) {
        float mx = acc[0]; int bi = 0;
#pragma unroll
        for (int e = 1; e < EDIM; e++) if (acc[e] > mx) { mx = acc[e]; bi = e; }
        float g[EDIM], sum = 0.f;
#pragma unroll
        for (int e = 0; e < EDIM; e++) { g[e] = expf(acc[e] - mx); sum += g[e]; }
        float inv = 1.f / sum;
#pragma unroll
        for (int e = 0; e < EDIM; e++) { g[e] *= inv; atomicAdd(&ssum[e], g[e]); }
        atomicAdd(&scnt[bi], 1);
        g_exp[t]  = bi;
        g_gate[t] = g[bi];
    }
    __syncthreads();
    if (tid < EDIM) {
        atomicAdd(&g_sumgate[tid], ssum[tid]);
        atomicAdd(&g_count[tid], scnt[tid]);
    }
}

__global__ __launch_bounds__(256) void scan_kernel() {
    __shared__ int sc[256][EDIM];
    int tid = threadIdx.x;
    int t0 = tid * 32;
    int cnt[EDIM];
#pragma unroll
    for (int e = 0; e < EDIM; e++) cnt[e] = 0;
    for (int j = 0; j < 32; j++) cnt[g_exp[t0 + j]]++;
#pragma unroll
    for (int e = 0; e < EDIM; e++) sc[tid][e] = cnt[e];
    __syncthreads();
    if (tid < EDIM) {
        int run = 0;
        for (int i = 0; i < 256; i++) { int c = sc[i][tid]; sc[i][tid] = run; run += c; }
    }
    __syncthreads();
    int base[EDIM];
#pragma unroll
    for (int e = 0; e < EDIM; e++) base[e] = sc[tid][e];
    for (int j = 0; j < 32; j++) {
        int t = t0 + j;
        int e = g_exp[t];
        int loc = base[e]++;
        g_loc[t] = loc;
        if (loc >= CAP) g_gate[t] = 0.f;
    }
    if (tid == 0) {
        float l = 0.f;
        for (int e = 0; e < EDIM; e++)
            l += (g_sumgate[e] / (float)S_TOK) * ((float)g_count[e] / (float)S_TOK);
        g_laux = l * (float)EDIM;
    }
}

// dispatch: gather kept tokens into split-bf16 rows of g_disp
__global__ __launch_bounds__(256) void scatter_kernel(const float* __restrict__ x) {
    int t = blockIdx.x;
    float g = g_gate[t];
    if (g <= 0.f) return;
    int e = g_exp[t], loc = g_loc[t];
    int tid = threadIdx.x;
    float4 v = ((const float4*)(x + (size_t)t * MDIM))[tid];
    uint32_t h0, l0, h1, l1;
    split2(v.x, v.y, h0, l0);
    split2(v.z, v.w, h1, l1);
    uint32_t* row = g_disp + ((size_t)e * CAP + loc) * MDIM;   // rowu32 = 1024
    row[tid * 2]       = h0;
    row[tid * 2 + 1]   = h1;
    row[512 + tid * 2]     = l0;
    row[512 + tid * 2 + 1] = l1;
}

// ======================= bf16-split mma GEMM ===============================
// C[8192, N] = A[8192, K] @ Wexp[K, N] via 3 bf16 products (hh + hl + lh)
// A: split rows (rowu32=K), B: Wt split rows [n][k] (rowu32=K)
// BM=BN=128, BK=32, 256 thr (8 warps 2x4), warp tile 64x32, 2-stage cp.async
// smem stage: A 16KB + B 16KB; row = 128B = [hi 4 chunks][lo 4 chunks],
// chunk phys = logical ^ (row & 7)
static constexpr int GSMEM_BYTES = 65536 + 1024;

template <int K, int N, bool SPLIT_OUT>
__global__ __launch_bounds__(256, 2) void mma_gemm(const uint32_t* __restrict__ A,
                                                   const uint32_t* __restrict__ B,
                                                   void* __restrict__ Cv) {
    extern __shared__ char dynsmem[];
    char* sptr = (char*)((((uintptr_t)dynsmem) + 1023) & ~(uintptr_t)1023);
    uint32_t sbase = smem_u32(sptr);

    int tid = threadIdx.x;
    int wid = tid >> 5, lane = tid & 31;
    int row0 = blockIdx.y * 128, col0 = blockIdx.x * 128;
    const uint32_t* __restrict__ Be = B + (size_t)(blockIdx.y >> 3) * ((size_t)N * K);

    // ---- loader: thread t covers row lm, half lh (0=hi,1=lo), 4 chunks each op
    int lm = tid >> 1;
    int lh = tid & 1;
    const char* Ab = (const char*)(A + (size_t)(row0 + lm) * K) + lh * 2 * K;
    const char* Bb = (const char*)(Be + (size_t)(col0 + lm) * K) + lh * 2 * K;
    uint32_t swz = (uint32_t)(lm & 7);
    uint32_t dA = sbase + (uint32_t)lm * 128u;
    uint32_t dB = sbase + 16384u + (uint32_t)lm * 128u;

    auto load_tile = [&](int kt, int buf) {
        const char* As = Ab + kt * 64;       // 32 k * 2B
        const char* Bs = Bb + kt * 64;
        uint32_t off = (uint32_t)buf * 32768u;
#pragma unroll
        for (int c8 = 0; c8 < 4; c8++) {
            uint32_t p = (((uint32_t)(lh * 4 + c8)) ^ swz) << 4;
            cp_async16(dA + off + p, As + c8 * 16);
            cp_async16(dB + off + p, Bs + c8 * 16);
        }
        CP_COMMIT();
    };

    int wm = (wid & 1) * 64;
    int wn = (wid >> 1) * 32;

    float acc[4][4][4];
#pragma unroll
    for (int i = 0; i < 4; i++)
#pragma unroll
        for (int j = 0; j < 4; j++)
#pragma unroll
            for (int q = 0; q < 4; q++) acc[i][j][q] = 0.f;

    load_tile(0, 0);

    constexpr int KT = K / 32;
#pragma unroll 1
    for (int kt = 0; kt < KT; kt++) {
        int buf = kt & 1;
        if (kt + 1 < KT) { load_tile(kt + 1, buf ^ 1); CP_WAIT(1); }
        else             { CP_WAIT(0); }
        __syncthreads();

        uint32_t sA = sbase + (uint32_t)buf * 32768u;
        uint32_t sB = sA + 16384u;

        // B fragments (all 32 k, both operands): 8x ldmatrix.x4
        uint32_t bh[4][4], bl[4][4];
#pragma unroll
        for (int jt = 0; jt < 4; jt++) {
            uint32_t row = (uint32_t)(wn + jt * 8 + (lane & 7));
            uint32_t c = (uint32_t)(lane >> 3);
            uint32_t rbase = sB + row * 128u;
            uint32_t rsw = row & 7u;
            ldmatrix_x4(bh[jt], rbase + ((c ^ rsw) << 4));
            ldmatrix_x4(bl[jt], rbase + (((c + 4u) ^ rsw) << 4));
        }

#pragma unroll
        for (int mi = 0; mi < 4; mi++) {
#pragma unroll
            for (int s = 0; s < 2; s++) {
                uint32_t row = (uint32_t)(wm + mi * 16 + (lane & 15));
                uint32_t c = (uint32_t)(2 * s + (lane >> 4));
                uint32_t rbase = sA + row * 128u;
                uint32_t rsw = row & 7u;
                uint32_t ah[4], al[4];
                ldmatrix_x4(ah, rbase + ((c ^ rsw) << 4));
                ldmatrix_x4(al, rbase + (((c + 4u) ^ rsw) << 4));
#pragma unroll
                for (int jt = 0; jt < 4; jt++) {
                    mma_bf16(acc[mi][jt], ah, bh[jt][2 * s], bh[jt][2 * s + 1]);
                    mma_bf16(acc[mi][jt], ah, bl[jt][2 * s], bl[jt][2 * s + 1]);
                    mma_bf16(acc[mi][jt], al, bh[jt][2 * s], bh[jt][2 * s + 1]);
                }
            }
        }
        __syncthreads();
    }

    // ---- epilogue ----
#pragma unroll
    for (int mi = 0; mi < 4; mi++) {
        int r = row0 + wm + mi * 16 + (lane >> 2);
#pragma unroll
        for (int jt = 0; jt < 4; jt++) {
            int c = col0 + wn + jt * 8 + (lane & 3) * 2;
            float v0 = acc[mi][jt][0], v1 = acc[mi][jt][1];
            float v2 = acc[mi][jt][2], v3 = acc[mi][jt][3];
            if (SPLIT_OUT) {
                uint32_t* C = (uint32_t*)Cv;   // rowu32 = N
                uint32_t hi, lo;
                split2(fmaxf(v0, 0.f), fmaxf(v1, 0.f), hi, lo);
                size_t b0 = (size_t)r * N + (c >> 1);
                C[b0] = hi; C[b0 + N / 2] = lo;
                split2(fmaxf(v2, 0.f), fmaxf(v3, 0.f), hi, lo);
                size_t b1 = (size_t)(r + 8) * N + (c >> 1);
                C[b1] = hi; C[b1 + N / 2] = lo;
            } else {
                float* C = (float*)Cv;
                *(float2*)(C + (size_t)r * N + c)       = make_float2(v0, v1);
                *(float2*)(C + (size_t)(r + 8) * N + c) = make_float2(v2, v3);
            }
        }
    }
}

// ======================= combine ===========================================
__global__ __launch_bounds__(256) void combine_kernel(float* __restrict__ out, int out_size) {
    int t = blockIdx.x;
    float g = g_gate[t];
    float4* dst = (float4*)(out + (size_t)t * MDIM);
    if (g > 0.f) {
        int e = g_exp[t], loc = g_loc[t];
        const float4* src = (const float4*)(g_eout + ((size_t)e * CAP + loc) * MDIM);
        float4 v = src[threadIdx.x];
        v.x *= g; v.y *= g; v.z *= g; v.w *= g;
        dst[threadIdx.x] = v;
    } else {
        dst[threadIdx.x] = make_float4(0.f, 0.f, 0.f, 0.f);
    }
    if (blockIdx.x == 0 && threadIdx.x == 0 && out_size > S_TOK * MDIM)
        out[(size_t)S_TOK * MDIM] = g_laux;
}

// ======================= launch ============================================
extern "C" void kernel_launch(void* const* d_in, const int* in_sizes, int n_in,
                              void* d_out, int out_size) {
    const float* x  = (const float*)d_in[0];   // [4,2048,1024]
    const float* wg = (const float*)d_in[1];   // [1024,8]
    const float* w1 = (const float*)d_in[2];   // [8,1024,4096]
    const float* w2 = (const float*)d_in[3];   // [8,4096,1024]
    float* out = (float*)d_out;

    uint32_t *p_disp, *p_h, *p_w1t, *p_w2t;
    float* p_eout;
    cudaGetSymbolAddress((void**)&p_disp, g_disp);
    cudaGetSymbolAddress((void**)&p_h,    g_h);
    cudaGetSymbolAddress((void**)&p_eout, g_eout);
    cudaGetSymbolAddress((void**)&p_w1t,  g_w1t);
    cudaGetSymbolAddress((void**)&p_w2t,  g_w2t);

    static bool attr_done = false;
    if (!attr_done) {
        cudaFuncSetAttribute(mma_gemm<MDIM, HDIM, true>,
                             cudaFuncAttributeMaxDynamicSharedMemorySize, GSMEM_BYTES);
        cudaFuncSetAttribute(mma_gemm<HDIM, MDIM, false>,
                             cudaFuncAttributeMaxDynamicSharedMemorySize, GSMEM_BYTES);
        attr_done = true;
    }

    // weight transpose + split (every launch; graph-capturable)
    wsplit_kernel<MDIM, HDIM><<<dim3(HDIM / 32, MDIM / 32, EDIM), dim3(32, 8)>>>(w1, p_w1t);
    wsplit_kernel<HDIM, MDIM><<<dim3(MDIM / 32, HDIM / 32, EDIM), dim3(32, 8)>>>(w2, p_w2t);

    init_kernel<<<1, 32>>>();
    gate_kernel<<<S_TOK / 8, 256>>>(x, wg);
    scan_kernel<<<1, 256>>>();
    scatter_kernel<<<S_TOK, 256>>>(x);
    mma_gemm<MDIM, HDIM, true><<<dim3(HDIM / 128, S_TOK / 128), 256, GSMEM_BYTES>>>(p_disp, p_w1t, p_h);
    mma_gemm<HDIM, MDIM, false><<<dim3(MDIM / 128, S_TOK / 128), 256, GSMEM_BYTES>>>(p_h, p_w2t, p_eout);
    combine_kernel<<<S_TOK, 256>>>(out, out_size);
}

// round 5
// speedup vs baseline: 2.9865x; 2.9865x over previous
#include <cuda_runtime.h>
#include <cuda_fp16.h>
#include <cstdint>

#define S_TOK 8192
#define MDIM  1024
#define EDIM  8
#define HDIM  4096
#define CAP   1024

// ======================= helpers ===========================================
__device__ __forceinline__ uint32_t smem_u32(const void* p) {
    uint32_t a;
    asm("{ .reg .u64 t; cvta.to.shared.u64 t, %1; cvt.u32.u64 %0, t; }" : "=r"(a) : "l"(p));
    return a;
}
__device__ __forceinline__ void cp_async16(uint32_t dst, const void* src) {
    asm volatile("cp.async.cg.shared.global [%0], [%1], 16;" :: "r"(dst), "l"(src));
}
#define CP_COMMIT() asm volatile("cp.async.commit_group;" ::: "memory")
#define CP_WAIT(n)  asm volatile("cp.async.wait_group %0;" :: "n"(n) : "memory")

__device__ __forceinline__ void ldmatrix_x4(uint32_t* r, uint32_t addr) {
    asm volatile("ldmatrix.sync.aligned.m8n8.x4.shared.b16 {%0,%1,%2,%3}, [%4];"
                 : "=r"(r[0]), "=r"(r[1]), "=r"(r[2]), "=r"(r[3]) : "r"(addr));
}
__device__ __forceinline__ void mma_fp16(float* c, const uint32_t* a, uint32_t b0, uint32_t b1) {
    asm volatile("mma.sync.aligned.m16n8k16.row.col.f32.f16.f16.f32 "
                 "{%0,%1,%2,%3}, {%4,%5,%6,%7}, {%8,%9}, {%0,%1,%2,%3};"
                 : "+f"(c[0]), "+f"(c[1]), "+f"(c[2]), "+f"(c[3])
                 : "r"(a[0]), "r"(a[1]), "r"(a[2]), "r"(a[3]), "r"(b0), "r"(b1));
}

// ======================= scratch ===========================================
__device__ float g_gate[S_TOK];
__device__ int   g_exp[S_TOK];
__device__ int   g_loc[S_TOK];
__device__ float g_sumgate[EDIM];
__device__ int   g_count[EDIM];
__device__ float g_laux;
__device__ __half g_disp[(size_t)EDIM * CAP * MDIM];   // fp16 dispatch (16MB)
__device__ __half g_h[(size_t)S_TOK * HDIM];           // fp16 hidden   (64MB)
__device__ float  g_eout[(size_t)S_TOK * MDIM];        // fp32          (32MB)
__device__ __half g_w1t[(size_t)EDIM * HDIM * MDIM];   // [e][n=4096][k=1024] (64MB)
__device__ __half g_w2t[(size_t)EDIM * MDIM * HDIM];   // [e][n=1024][k=4096] (64MB)

// ======================= weight transpose + fp16 convert ===================
// W[e][K][N] fp32 -> Wt[e][N][K] fp16
template <int K, int N>
__global__ __launch_bounds__(256) void wconv_kernel(const float* __restrict__ W,
                                                    __half* __restrict__ Wt) {
    __shared__ float tile[32][33];
    int e = blockIdx.z;
    const float* We = W + (size_t)e * K * N;
    __half* Wte = Wt + (size_t)e * N * K;
    int n0 = blockIdx.x * 32, k0 = blockIdx.y * 32;
    int tx = threadIdx.x, ty = threadIdx.y;
#pragma unroll
    for (int j = 0; j < 32; j += 8)
        tile[ty + j][tx] = We[(size_t)(k0 + ty + j) * N + n0 + tx];
    __syncthreads();
#pragma unroll
    for (int j = 0; j < 32; j += 8)
        Wte[(size_t)(n0 + ty + j) * K + k0 + tx] = __float2half_rn(tile[tx][ty + j]);
}

// ======================= init / gating / scan ==============================
__global__ void init_kernel() {
    int t = threadIdx.x;
    if (t < EDIM) { g_sumgate[t] = 0.f; g_count[t] = 0; }
}

__global__ __launch_bounds__(256) void gate_kernel(const float* __restrict__ x,
                                                   const float* __restrict__ wg) {
    __shared__ float swg[MDIM * EDIM];
    __shared__ float ssum[EDIM];
    __shared__ int   scnt[EDIM];
    int tid = threadIdx.x;
    for (int i = tid; i < MDIM * EDIM; i += 256) swg[i] = wg[i];
    if (tid < EDIM) { ssum[tid] = 0.f; scnt[tid] = 0; }
    __syncthreads();

    int warp = tid >> 5, lane = tid & 31;
    int t = blockIdx.x * 8 + warp;
    const float* xr = x + (size_t)t * MDIM;

    float acc[EDIM];
#pragma unroll
    for (int e = 0; e < EDIM; e++) acc[e] = 0.f;
    for (int m = lane; m < MDIM; m += 32) {
        float xv = xr[m];
#pragma unroll
        for (int e = 0; e < EDIM; e++) acc[e] = fmaf(xv, swg[m * EDIM + e], acc[e]);
    }
#pragma unroll
    for (int e = 0; e < EDIM; e++)
#pragma unroll
        for (int o = 16; o > 0; o >>= 1)
            acc[e] += __shfl_xor_sync(0xffffffffu, acc[e], o);

    if (lane == 0) {
        float mx = acc[0]; int bi = 0;
#pragma unroll
        for (int e = 1; e < EDIM; e++) if (acc[e] > mx) { mx = acc[e]; bi = e; }
        float g[EDIM], sum = 0.f;
#pragma unroll
        for (int e = 0; e < EDIM; e++) { g[e] = expf(acc[e] - mx); sum += g[e]; }
        float inv = 1.f / sum;
#pragma unroll
        for (int e = 0; e < EDIM; e++) { g[e] *= inv; atomicAdd(&ssum[e], g[e]); }
        atomicAdd(&scnt[bi], 1);
        g_exp[t]  = bi;
        g_gate[t] = g[bi];
    }
    __syncthreads();
    if (tid < EDIM) {
        atomicAdd(&g_sumgate[tid], ssum[tid]);
        atomicAdd(&g_count[tid], scnt[tid]);
    }
}

__global__ __launch_bounds__(256) void scan_kernel() {
    __shared__ int sc[256][EDIM];
    int tid = threadIdx.x;
    int t0 = tid * 32;
    int cnt[EDIM];
#pragma unroll
    for (int e = 0; e < EDIM; e++) cnt[e] = 0;
    for (int j = 0; j < 32; j++) cnt[g_exp[t0 + j]]++;
#pragma unroll
    for (int e = 0; e < EDIM; e++) sc[tid][e] = cnt[e];
    __syncthreads();
    if (tid < EDIM) {
        int run = 0;
        for (int i = 0; i < 256; i++) { int c = sc[i][tid]; sc[i][tid] = run; run += c; }
    }
    __syncthreads();
    int base[EDIM];
#pragma unroll
    for (int e = 0; e < EDIM; e++) base[e] = sc[tid][e];
    for (int j = 0; j < 32; j++) {
        int t = t0 + j;
        int e = g_exp[t];
        int loc = base[e]++;
        g_loc[t] = loc;
        if (loc >= CAP) g_gate[t] = 0.f;
    }
    if (tid == 0) {
        float l = 0.f;
        for (int e = 0; e < EDIM; e++)
            l += (g_sumgate[e] / (float)S_TOK) * ((float)g_count[e] / (float)S_TOK);
        g_laux = l * (float)EDIM;
    }
}

// dispatch: gather kept tokens as fp16 rows
__global__ __launch_bounds__(256) void scatter_kernel(const float* __restrict__ x) {
    int t = blockIdx.x;
    float g = g_gate[t];
    if (g <= 0.f) return;
    int e = g_exp[t], loc = g_loc[t];
    int tid = threadIdx.x;
    float4 v = ((const float4*)(x + (size_t)t * MDIM))[tid];
    __half2* row = (__half2*)(g_disp + ((size_t)e * CAP + loc) * MDIM);
    row[tid * 2]     = __floats2half2_rn(v.x, v.y);
    row[tid * 2 + 1] = __floats2half2_rn(v.z, v.w);
}

// ======================= fp16 mma GEMM =====================================
// C[8192, N] = A[8192, K] @ Wexp[K, N], fp16 inputs, f32 accum
// A: fp16 rows [.][K]; B: Wt [e][n][K] fp16
// BM=BN=128, BK=64 (row=128B), 256 thr (8 warps 2x4), warp tile 64x32
// 2-stage cp.async; smem stage: A 16KB + B 16KB; chunk phys = logical^(row&7)
static constexpr int GSMEM_BYTES = 65536 + 1024;

template <int K, int N, bool RELU16>
__global__ __launch_bounds__(256, 2) void mma_gemm(const __half* __restrict__ A,
                                                   const __half* __restrict__ B,
                                                   void* __restrict__ Cv) {
    extern __shared__ char dynsmem[];
    char* sptr = (char*)((((uintptr_t)dynsmem) + 1023) & ~(uintptr_t)1023);
    uint32_t sbase = smem_u32(sptr);

    int tid = threadIdx.x;
    int wid = tid >> 5, lane = tid & 31;
    int row0 = blockIdx.y * 128, col0 = blockIdx.x * 128;
    const __half* __restrict__ Be = B + (size_t)(blockIdx.y >> 3) * ((size_t)N * K);

    // ---- loader: thread covers row lm, chunk-half lh (4 chunks per operand)
    int lm = tid >> 1;
    int lh = tid & 1;
    const char* Ab = (const char*)(A + (size_t)(row0 + lm) * K);
    const char* Bb = (const char*)(Be + (size_t)(col0 + lm) * K);
    uint32_t swz = (uint32_t)(lm & 7);
    uint32_t dA = sbase + (uint32_t)lm * 128u;
    uint32_t dB = sbase + 16384u + (uint32_t)lm * 128u;

    auto load_tile = [&](int kt, int buf) {
        const char* As = Ab + kt * 128;      // 64 k * 2B
        const char* Bs = Bb + kt * 128;
        uint32_t off = (uint32_t)buf * 32768u;
#pragma unroll
        for (int c8 = 0; c8 < 4; c8++) {
            uint32_t lc = (uint32_t)(lh * 4 + c8);
            uint32_t p = (lc ^ swz) << 4;
            cp_async16(dA + off + p, As + lc * 16);
            cp_async16(dB + off + p, Bs + lc * 16);
        }
        CP_COMMIT();
    };

    int wm = (wid & 1) * 64;
    int wn = (wid >> 1) * 32;

    float acc[4][4][4];
#pragma unroll
    for (int i = 0; i < 4; i++)
#pragma unroll
        for (int j = 0; j < 4; j++)
#pragma unroll
            for (int q = 0; q < 4; q++) acc[i][j][q] = 0.f;

    load_tile(0, 0);

    constexpr int KT = K / 64;
#pragma unroll 1
    for (int kt = 0; kt < KT; kt++) {
        int buf = kt & 1;
        if (kt + 1 < KT) { load_tile(kt + 1, buf ^ 1); CP_WAIT(1); }
        else             { CP_WAIT(0); }
        __syncthreads();

        uint32_t sA = sbase + (uint32_t)buf * 32768u;
        uint32_t sB = sA + 16384u;

        // process k in two 32-wide halves to cap register pressure
#pragma unroll
        for (int kh = 0; kh < 2; kh++) {
            // B fragments for this k32: 4 jt x ldsm.x4 (regs = k8 blocks)
            uint32_t bf[4][4];
#pragma unroll
            for (int jt = 0; jt < 4; jt++) {
                uint32_t row = (uint32_t)(wn + jt * 8 + (lane & 7));
                uint32_t c = (uint32_t)(lane >> 3) + (uint32_t)kh * 4u;
                ldmatrix_x4(bf[jt], sB + row * 128u + ((c ^ (row & 7u)) << 4));
            }
#pragma unroll
            for (int mi = 0; mi < 4; mi++) {
                uint32_t row = (uint32_t)(wm + mi * 16 + (lane & 15));
                uint32_t rbase = sA + row * 128u;
                uint32_t rsw = row & 7u;
#pragma unroll
                for (int s = 0; s < 2; s++) {      // two k16 steps in this k32
                    uint32_t c = (uint32_t)(kh * 4 + 2 * s + (lane >> 4));
                    uint32_t af[4];
                    ldmatrix_x4(af, rbase + ((c ^ rsw) << 4));
#pragma unroll
                    for (int jt = 0; jt < 4; jt++)
                        mma_fp16(acc[mi][jt], af, bf[jt][2 * s], bf[jt][2 * s + 1]);
                }
            }
        }
        __syncthreads();
    }

    // ---- epilogue ----
#pragma unroll
    for (int mi = 0; mi < 4; mi++) {
        int r = row0 + wm + mi * 16 + (lane >> 2);
#pragma unroll
        for (int jt = 0; jt < 4; jt++) {
            int c = col0 + wn + jt * 8 + (lane & 3) * 2;
            float v0 = acc[mi][jt][0], v1 = acc[mi][jt][1];
            float v2 = acc[mi][jt][2], v3 = acc[mi][jt][3];
            if (RELU16) {
                __half* C = (__half*)Cv;
                *(__half2*)(C + (size_t)r * N + c) =
                    __floats2half2_rn(fmaxf(v0, 0.f), fmaxf(v1, 0.f));
                *(__half2*)(C + (size_t)(r + 8) * N + c) =
                    __floats2half2_rn(fmaxf(v2, 0.f), fmaxf(v3, 0.f));
            } else {
                float* C = (float*)Cv;
                *(float2*)(C + (size_t)r * N + c)       = make_float2(v0, v1);
                *(float2*)(C + (size_t)(r + 8) * N + c) = make_float2(v2, v3);
            }
        }
    }
}

// ======================= combine ===========================================
__global__ __launch_bounds__(256) void combine_kernel(float* __restrict__ out, int out_size) {
    int t = blockIdx.x;
    float g = g_gate[t];
    float4* dst = (float4*)(out + (size_t)t * MDIM);
    if (g > 0.f) {
        int e = g_exp[t], loc = g_loc[t];
        const float4* src = (const float4*)(g_eout + ((size_t)e * CAP + loc) * MDIM);
        float4 v = src[threadIdx.x];
        v.x *= g; v.y *= g; v.z *= g; v.w *= g;
        dst[threadIdx.x] = v;
    } else {
        dst[threadIdx.x] = make_float4(0.f, 0.f, 0.f, 0.f);
    }
    if (blockIdx.x == 0 && threadIdx.x == 0 && out_size > S_TOK * MDIM)
        out[(size_t)S_TOK * MDIM] = g_laux;
}

// ======================= launch ============================================
extern "C" void kernel_launch(void* const* d_in, const int* in_sizes, int n_in,
                              void* d_out, int out_size) {
    const float* x  = (const float*)d_in[0];   // [4,2048,1024]
    const float* wg = (const float*)d_in[1];   // [1024,8]
    const float* w1 = (const float*)d_in[2];   // [8,1024,4096]
    const float* w2 = (const float*)d_in[3];   // [8,4096,1024]
    float* out = (float*)d_out;

    __half *p_disp, *p_h, *p_w1t, *p_w2t;
    float* p_eout;
    cudaGetSymbolAddress((void**)&p_disp, g_disp);
    cudaGetSymbolAddress((void**)&p_h,    g_h);
    cudaGetSymbolAddress((void**)&p_eout, g_eout);
    cudaGetSymbolAddress((void**)&p_w1t,  g_w1t);
    cudaGetSymbolAddress((void**)&p_w2t,  g_w2t);

    static bool attr_done = false;
    if (!attr_done) {
        cudaFuncSetAttribute(mma_gemm<MDIM, HDIM, true>,
                             cudaFuncAttributeMaxDynamicSharedMemorySize, GSMEM_BYTES);
        cudaFuncSetAttribute(mma_gemm<HDIM, MDIM, false>,
                             cudaFuncAttributeMaxDynamicSharedMemorySize, GSMEM_BYTES);
        attr_done = true;
    }

    // weight transpose + fp16 convert
    wconv_kernel<MDIM, HDIM><<<dim3(HDIM / 32, MDIM / 32, EDIM), dim3(32, 8)>>>(w1, p_w1t);
    wconv_kernel<HDIM, MDIM><<<dim3(MDIM / 32, HDIM / 32, EDIM), dim3(32, 8)>>>(w2, p_w2t);

    init_kernel<<<1, 32>>>();
    gate_kernel<<<S_TOK / 8, 256>>>(x, wg);
    scan_kernel<<<1, 256>>>();
    scatter_kernel<<<S_TOK, 256>>>(x);
    mma_gemm<MDIM, HDIM, true><<<dim3(HDIM / 128, S_TOK / 128), 256, GSMEM_BYTES>>>(p_disp, p_w1t, p_h);
    mma_gemm<HDIM, MDIM, false><<<dim3(MDIM / 128, S_TOK / 128), 256, GSMEM_BYTES>>>(p_h, p_w2t, p_eout);
    combine_kernel<<<S_TOK, 256>>>(out, out_size);
}